// round 8
// baseline (speedup 1.0000x reference)
#include <cuda_runtime.h>
#include <math_constants.h>

// Problem constants
#define NSL     24
#define BB      16
#define CCH     512
#define HWN     256          // H*W
#define FEAT_IN 1024
#define CLASSES 3
#define CG      8            // c-values per CTA (one per warp)
#define CTAS_PER_B (CCH / CG)       // 64
#define GRID    (BB * CTAS_PER_B)   // 1024
#define SLICE_STRIDE ((size_t)BB * CCH * HWN)   // floats per slice (2M)

// Persistent scratch (zero at module load; each launch restores it to zero).
__device__ float        g_acc[BB * CLASSES];
__device__ unsigned int g_count[BB];

// Fused kernel: 1024 CTAs x 256 threads, one wave. Warp owns channel c.
// - Slice start rotated per CTA (gid % 24): instantaneous DRAM footprint
//   spans all 192MB, decorrelating channel/row pressure. Max is order-
//   independent so results are bit-identical.
// - Software-pipelined: segment i+1's two LDG.128 are issued BEFORE the
//   shuffle-reduction chain of segment i, guaranteeing the memory pipe
//   never drains behind the SHFL dependency chain.
__global__ __launch_bounds__(256, 7) void fused_kernel(
    const float* __restrict__ feat_f_map,
    const float* __restrict__ oct_maps,
    const float* __restrict__ head_w,
    const float* __restrict__ head_b,
    float* __restrict__ out)
{
    const int gid  = blockIdx.x;          // 0..1023
    const int b    = gid >> 6;            // / 64
    const int cg   = gid & 63;            // % 64
    const int warp = threadIdx.x >> 5;    // 0..7
    const int lane = threadIdx.x & 31;
    const int c    = cg * CG + warp;      // this warp's channel
    const int s0   = gid % NSL;           // slice rotation offset

    const size_t bc_off = ((size_t)(b * CCH + c)) << 8;   // *HWN
    const float* oct_bc = oct_maps + bc_off;

    // Prologue: issue loads for the first oct segment.
    {
        const float4* p = (const float4*)(oct_bc + (size_t)s0 * SLICE_STRIDE);
        float4 a0 = p[lane], a1 = p[lane + 32];

        float vmax = -CUDART_INF_F;
        #pragma unroll
        for (int i = 0; i < NSL; i++) {
            // Issue next segment's loads before reducing the current one.
            float4 n0, n1;
            if (i + 1 < NSL) {
                int sn = s0 + i + 1; if (sn >= NSL) sn -= NSL;
                const float4* pn = (const float4*)(oct_bc + (size_t)sn * SLICE_STRIDE);
                n0 = pn[lane]; n1 = pn[lane + 32];
            }
            float t = ((a0.x + a0.y) + (a0.z + a0.w))
                    + ((a1.x + a1.y) + (a1.z + a1.w));
            #pragma unroll
            for (int off = 16; off; off >>= 1)
                t += __shfl_xor_sync(0xffffffffu, t, off);
            vmax = fmaxf(vmax, t);
            if (i + 1 < NSL) { a0 = n0; a1 = n1; }
        }

        // feat_f segment: contiguous 1KB
        float sff;
        {
            const float4* p4 = (const float4*)(feat_f_map + bc_off);
            float4 v0 = p4[lane], v1 = p4[lane + 32];
            float s = ((v0.x + v0.y) + (v0.z + v0.w))
                    + ((v1.x + v1.y) + (v1.z + v1.w));
            #pragma unroll
            for (int off = 16; off; off >>= 1)
                s += __shfl_xor_sync(0xffffffffu, s, off);
            sff = s;
        }

        // Head contribution for this c (lane 0 of each warp) -> shared acc
        __shared__ float    s_acc[CLASSES];
        __shared__ unsigned s_ticket;
        if (threadIdx.x < CLASSES) s_acc[threadIdx.x] = 0.f;
        __syncthreads();

        if (lane == 0) {
            const float inv = 1.0f / (float)HWN;
            const float ff = sff  * inv;      // feat_f[b][c]
            const float fo = vmax * inv;      // feat_o[b][c] = max_s mean_HW
            #pragma unroll
            for (int cl = 0; cl < CLASSES; cl++) {
                const float* w = head_w + cl * FEAT_IN;
                atomicAdd(&s_acc[cl], ff * w[c] + fo * w[CCH + c]);
            }
        }
        __syncthreads();

        if (threadIdx.x < CLASSES)
            atomicAdd(&g_acc[b * CLASSES + threadIdx.x], s_acc[threadIdx.x]);

        // Per-b completion ticket (release: fence before counter increment)
        __threadfence();
        if (threadIdx.x == 0)
            s_ticket = atomicAdd(&g_count[b], 1u);
        __syncthreads();

        if (s_ticket == CTAS_PER_B - 1) {
            // Last CTA of this b: finalize outputs, restore scratch state.
            if (threadIdx.x < CLASSES) {
                float v = atomicExch(&g_acc[b * CLASSES + threadIdx.x], 0.f);
                out[b * CLASSES + threadIdx.x] = v + head_b[threadIdx.x];
            }
            if (threadIdx.x == 0)
                atomicExch(&g_count[b], 0u);
        }
    }
}

extern "C" void kernel_launch(void* const* d_in, const int* in_sizes, int n_in,
                              void* d_out, int out_size)
{
    const float* feat_f_map = (const float*)d_in[0];  // (16,512,16,16)
    const float* oct_maps   = (const float*)d_in[1];  // (24,16,512,16,16)
    const float* head_w     = (const float*)d_in[2];  // (3,1024)
    const float* head_b     = (const float*)d_in[3];  // (3,)
    float* out = (float*)d_out;                        // (16,3)

    fused_kernel<<<GRID, 256>>>(feat_f_map, oct_maps, head_w, head_b, out);
}

// round 9
// speedup vs baseline: 1.0049x; 1.0049x over previous
#include <cuda_runtime.h>
#include <math_constants.h>

// Problem constants
#define NSL     24
#define BB      16
#define CCH     512
#define HWN     256          // H*W
#define FEAT_IN 1024
#define CLASSES 3
#define CG      8            // c-values per CTA (one per warp)
#define CTAS_PER_B (CCH / CG)       // 64
#define GRID    (BB * CTAS_PER_B)   // 1024
#define SLICE_STRIDE ((size_t)BB * CCH * HWN)   // floats per slice (2M)

// Persistent scratch (zero at module load; each launch restores it to zero).
__device__ float        g_acc[BB * CLASSES];
__device__ unsigned int g_count[BB];

// Fused kernel: 1024 CTAs x 256 threads, one wave. Warp owns channel c.
// Each CTA starts its slice loop at a rotated offset (gid % 24) so the
// grid's instantaneous DRAM footprint spans all 24 slices (192MB) instead
// of one hot 8MB slice window. Max over slices is order-independent, so
// the result is bit-identical. Loads are left to ptxas's own front-batching
// (#pragma unroll 3) — hand pipelining measurably regressed (R8).
__global__ __launch_bounds__(256, 7) void fused_kernel(
    const float* __restrict__ feat_f_map,
    const float* __restrict__ oct_maps,
    const float* __restrict__ head_w,
    const float* __restrict__ head_b,
    float* __restrict__ out)
{
    const int gid  = blockIdx.x;          // 0..1023
    const int b    = gid >> 6;            // / 64
    const int cg   = gid & 63;            // % 64
    const int warp = threadIdx.x >> 5;    // 0..7
    const int lane = threadIdx.x & 31;
    const int c    = cg * CG + warp;      // this warp's channel
    const int s0   = gid % NSL;           // slice rotation offset

    const size_t bc_off = ((size_t)(b * CCH + c)) << 8;   // *HWN

    // feat_f segment: contiguous 1KB
    float sff;
    {
        const float4* p4 = (const float4*)(feat_f_map + bc_off);
        float4 v0 = p4[lane], v1 = p4[lane + 32];
        float s = ((v0.x + v0.y) + (v0.z + v0.w))
                + ((v1.x + v1.y) + (v1.z + v1.w));
        #pragma unroll
        for (int off = 16; off; off >>= 1)
            s += __shfl_xor_sync(0xffffffffu, s, off);
        sff = s;
    }

    // 24 oct slices (rotated order): max over slice sums
    float vmax = -CUDART_INF_F;
    #pragma unroll 3
    for (int i = 0; i < NSL; i++) {
        int s = s0 + i; if (s >= NSL) s -= NSL;
        const float4* p = (const float4*)
            (oct_maps + (size_t)s * SLICE_STRIDE + bc_off);
        float4 v0 = p[lane], v1 = p[lane + 32];
        float t = ((v0.x + v0.y) + (v0.z + v0.w))
                + ((v1.x + v1.y) + (v1.z + v1.w));
        #pragma unroll
        for (int off = 16; off; off >>= 1)
            t += __shfl_xor_sync(0xffffffffu, t, off);
        vmax = fmaxf(vmax, t);
    }

    // Head contribution for this c (lane 0 of each warp) -> shared acc
    __shared__ float    s_acc[CLASSES];
    __shared__ unsigned s_ticket;
    if (threadIdx.x < CLASSES) s_acc[threadIdx.x] = 0.f;
    __syncthreads();

    if (lane == 0) {
        const float inv = 1.0f / (float)HWN;
        const float ff = sff  * inv;      // feat_f[b][c]
        const float fo = vmax * inv;      // feat_o[b][c] = max_s mean_HW
        #pragma unroll
        for (int cl = 0; cl < CLASSES; cl++) {
            const float* w = head_w + cl * FEAT_IN;
            atomicAdd(&s_acc[cl], ff * w[c] + fo * w[CCH + c]);
        }
    }
    __syncthreads();

    if (threadIdx.x < CLASSES)
        atomicAdd(&g_acc[b * CLASSES + threadIdx.x], s_acc[threadIdx.x]);

    // Per-b completion ticket (release: fence before counter increment)
    __threadfence();
    if (threadIdx.x == 0)
        s_ticket = atomicAdd(&g_count[b], 1u);
    __syncthreads();

    if (s_ticket == CTAS_PER_B - 1) {
        // Last CTA of this b: finalize its 3 outputs, restore scratch state.
        if (threadIdx.x < CLASSES) {
            float v = atomicExch(&g_acc[b * CLASSES + threadIdx.x], 0.f);
            out[b * CLASSES + threadIdx.x] = v + head_b[threadIdx.x];
        }
        if (threadIdx.x == 0)
            atomicExch(&g_count[b], 0u);
    }
}

extern "C" void kernel_launch(void* const* d_in, const int* in_sizes, int n_in,
                              void* d_out, int out_size)
{
    const float* feat_f_map = (const float*)d_in[0];  // (16,512,16,16)
    const float* oct_maps   = (const float*)d_in[1];  // (24,16,512,16,16)
    const float* head_w     = (const float*)d_in[2];  // (3,1024)
    const float* head_b     = (const float*)d_in[3];  // (3,)
    float* out = (float*)d_out;                        // (16,3)

    fused_kernel<<<GRID, 256>>>(feat_f_map, oct_maps, head_w, head_b, out);
}